// round 2
// baseline (speedup 1.0000x reference)
#include <cuda_runtime.h>
#include <cstdint>

// AF2dMADEBlock: autoregressive flow inversion via exact sequential raster sweep.
// The reference's 64-iteration fixed-point scan is mathematically identical to a
// single raster-order sequential pass because the PixelCNN masks zero all
// contributions from pixels >= current (mask A excludes center at layer 0).
//
// Grid: 64 CTAs = 32 batches x 2 nets (cluster of 2: rank0 = mu, rank1 = lv).
// 512 threads/CTA. Masked w1/w2 weights (5 taps x 64 in x 64 out) live in
// registers (80 float regs/thread); activations gathered into contiguous smem
// buffers and read with a conflict-free broadcast pattern.
// Per-pixel mu/logstd exchange between the two CTAs of a cluster via DSMEM
// stores + double-buffered mbarriers.

#define ELU_EPS 1e-12f

__device__ __forceinline__ uint32_t smem_u32(const void* p){
  return (uint32_t)__cvta_generic_to_shared((void*)p);
}

__global__ void __cluster_dims__(2,1,1) __launch_bounds__(512,1)
made_flow_kernel(const float* __restrict__ xg,
  const float* __restrict__ mw0, const float* __restrict__ mb0,
  const float* __restrict__ mw1, const float* __restrict__ mb1,
  const float* __restrict__ mw2, const float* __restrict__ mb2,
  const float* __restrict__ mwo, const float* __restrict__ mbo,
  const float* __restrict__ lw0, const float* __restrict__ lb0,
  const float* __restrict__ lw1, const float* __restrict__ lb1,
  const float* __restrict__ lw2, const float* __restrict__ lb2,
  const float* __restrict__ lwo, const float* __restrict__ lbo,
  float* __restrict__ out, int out_n)
{
  __shared__ __align__(16) float h0g[64*64];   // h0 over full 8x8 grid, [pix][ch]
  __shared__ __align__(16) float h1g[64*64];   // h1 over full 8x8 grid
  __shared__ __align__(16) float w0s[16*64];   // packed mask-A w0: [(tap*4+ic)][o]
  __shared__ __align__(16) float y_s[64*4];    // y, [pix][ch]
  __shared__ __align__(16) float x_s[64*4];    // x, [pix][ch]
  __shared__ __align__(16) float a_l1[320];    // gathered input window for layer1
  __shared__ __align__(16) float a_l2[320];    // gathered input window for layer2
  __shared__ __align__(16) float h2_s[64];
  __shared__ float b0s[64], b1s[64], b2s[64];
  __shared__ __align__(16) float wos[256];     // 1x1 out conv [oc][c]
  __shared__ float bos[4];
  __shared__ __align__(16) float myout[4];     // this net's 4 outputs at pixel p
  __shared__ __align__(16) float recvbuf[2][4];// peer's 4 outputs, dbl-buffered
  __shared__ __align__(8) unsigned long long mbar[2];

  const int tid = threadIdx.x;
  uint32_t rank; asm("mov.u32 %0, %%cluster_ctarank;" : "=r"(rank));
  const int batch = blockIdx.x >> 1;

  const float* w0g = rank ? lw0 : mw0;
  const float* b0g = rank ? lb0 : mb0;
  const float* w1g = rank ? lw1 : mw1;
  const float* b1g = rank ? lb1 : mb1;
  const float* w2g = rank ? lw2 : mw2;
  const float* b2g = rank ? lb2 : mb2;
  const float* wog = rank ? lwo : mwo;
  const float* bog = rank ? lbo : mbo;

  if (tid == 0){
    asm volatile("mbarrier.init.shared.b64 [%0], %1;"
                 :: "r"(smem_u32(&mbar[0])), "r"(1u) : "memory");
    asm volatile("mbarrier.init.shared.b64 [%0], %1;"
                 :: "r"(smem_u32(&mbar[1])), "r"(1u) : "memory");
  }

  // ---- Stage weights/biases/x into smem ----
  // w0 packed: tap t in {(-1,-1),(-1,0),(-1,1),(0,-1)} (mask A), transposed so
  // lanes (o consecutive) read conflict-free.
  for (int idx = tid; idx < 1024; idx += 512){
    int r = idx >> 6, o = idx & 63;
    int t = r >> 2, ic = r & 3;
    int ky = (t == 3) ? 1 : 0;
    int kx = (t == 3) ? 0 : t;
    w0s[idx] = w0g[(o*4 + ic)*9 + ky*3 + kx];
  }
  if (tid < 64){ b0s[tid] = b0g[tid]; b1s[tid] = b1g[tid]; b2s[tid] = b2g[tid]; }
  if (tid < 256) wos[tid] = wog[tid];
  if (tid < 4)   bos[tid] = bog[tid];
  if (tid < 256){
    int pos = tid & 63, c = tid >> 6;
    x_s[pos*4 + c] = xg[batch*256 + tid];   // NCHW -> [pix][ch]
  }

  // ---- Masked mask-B weights into registers ----
  // Thread (o = tid>>3, j = tid&7) owns K-slice {4j+32i+m : i<10, m<4} of the
  // 320-long dot for output channel o. k -> (tap = k>>6, ic = k&63);
  // taps in order (-1,-1),(-1,0),(-1,1),(0,-1),(0,0).
  const int o = tid >> 3;
  const int j = tid & 7;
  float4 w1r[10], w2r[10];
  #pragma unroll
  for (int i = 0; i < 10; i++){
    float t1[4], t2[4];
    #pragma unroll
    for (int m = 0; m < 4; m++){
      int k  = (j << 2) + (i << 5) + m;
      int t  = k >> 6, ic = k & 63;
      int ky = (t >= 3) ? 1 : 0;
      int kx = (t >= 3) ? (t - 3) : t;
      int gi = (o*64 + ic)*9 + ky*3 + kx;
      t1[m] = w1g[gi];
      t2[m] = w2g[gi];
    }
    w1r[i] = make_float4(t1[0], t1[1], t1[2], t1[3]);
    w2r[i] = make_float4(t2[0], t2[1], t2[2], t2[3]);
  }

  __syncthreads();
  // mbarrier init must be cluster-visible before any peer arrive.
  asm volatile("barrier.cluster.arrive.aligned;" ::: "memory");
  asm volatile("barrier.cluster.wait.aligned;"   ::: "memory");

  float lssum = 0.f;

  for (int p = 0; p < 64; p++){
    const int py = p >> 3, px = p & 7;

    // ---- Phase 1: h0[p] (threads 0..63) + past-tap gathers (threads 64..191)
    if (tid < 64){
      float acc = b0s[tid];
      #pragma unroll
      for (int t = 0; t < 4; t++){
        int qy = py + ((t < 3) ? -1 : 0);
        int qx = px + ((t < 3) ? (t - 1) : -1);
        if ((unsigned)qy < 8u && (unsigned)qx < 8u){
          int q = qy*8 + qx;
          const float* ww = &w0s[(t << 2)*64 + tid];
          const float* yy = &y_s[q << 2];
          acc = fmaf(ww[0],   yy[0], acc);
          acc = fmaf(ww[64],  yy[1], acc);
          acc = fmaf(ww[128], yy[2], acc);
          acc = fmaf(ww[192], yy[3], acc);
        }
      }
      float e = acc > 0.f ? acc : expm1f(acc);
      h0g[(p << 6) + tid] = e;
      a_l1[256 + tid] = e;            // center tap of layer-1 window
    } else if (tid < 192){
      int idx = tid - 64;             // 128 float4 gathers: 64 for a_l1, 64 for a_l2
      int buf = idx >> 6;
      int v   = idx & 63;
      int t   = v >> 4, c4 = (v & 15) << 2;
      int qy = py + ((t < 3) ? -1 : 0);
      int qx = px + ((t < 3) ? (t - 1) : -1);
      float4 val = make_float4(0.f, 0.f, 0.f, 0.f);
      const float* src = buf ? h1g : h0g;
      if ((unsigned)qy < 8u && (unsigned)qx < 8u)
        val = *(const float4*)&src[((qy*8 + qx) << 6) + c4];
      float* dst = buf ? a_l2 : a_l1;
      *(float4*)&dst[(t << 6) + c4] = val;
    }
    __syncthreads();

    // ---- Phase 2: h1[p] = ELU(W1 . a_l1 + b1), all 512 threads
    {
      float acc0 = 0.f, acc1 = 0.f;
      #pragma unroll
      for (int i = 0; i < 10; i += 2){
        float4 a = *(const float4*)&a_l1[(j << 2) + (i << 5)];
        float4 b = *(const float4*)&a_l1[(j << 2) + ((i + 1) << 5)];
        acc0 = fmaf(w1r[i].x,   a.x, acc0);
        acc0 = fmaf(w1r[i].y,   a.y, acc0);
        acc0 = fmaf(w1r[i].z,   a.z, acc0);
        acc0 = fmaf(w1r[i].w,   a.w, acc0);
        acc1 = fmaf(w1r[i+1].x, b.x, acc1);
        acc1 = fmaf(w1r[i+1].y, b.y, acc1);
        acc1 = fmaf(w1r[i+1].z, b.z, acc1);
        acc1 = fmaf(w1r[i+1].w, b.w, acc1);
      }
      float acc = acc0 + acc1;
      acc += __shfl_down_sync(0xffffffffu, acc, 4, 8);
      acc += __shfl_down_sync(0xffffffffu, acc, 2, 8);
      acc += __shfl_down_sync(0xffffffffu, acc, 1, 8);
      if (j == 0){
        float v = b1s[o] + acc;
        float e = v > 0.f ? v : expm1f(v);
        h1g[(p << 6) + o] = e;
        a_l2[256 + o] = e;            // center tap of layer-2 window
      }
    }
    __syncthreads();

    // ---- Phase 3: h2[p] = ELU(W2 . a_l2 + b2)
    {
      float acc0 = 0.f, acc1 = 0.f;
      #pragma unroll
      for (int i = 0; i < 10; i += 2){
        float4 a = *(const float4*)&a_l2[(j << 2) + (i << 5)];
        float4 b = *(const float4*)&a_l2[(j << 2) + ((i + 1) << 5)];
        acc0 = fmaf(w2r[i].x,   a.x, acc0);
        acc0 = fmaf(w2r[i].y,   a.y, acc0);
        acc0 = fmaf(w2r[i].z,   a.z, acc0);
        acc0 = fmaf(w2r[i].w,   a.w, acc0);
        acc1 = fmaf(w2r[i+1].x, b.x, acc1);
        acc1 = fmaf(w2r[i+1].y, b.y, acc1);
        acc1 = fmaf(w2r[i+1].z, b.z, acc1);
        acc1 = fmaf(w2r[i+1].w, b.w, acc1);
      }
      float acc = acc0 + acc1;
      acc += __shfl_down_sync(0xffffffffu, acc, 4, 8);
      acc += __shfl_down_sync(0xffffffffu, acc, 2, 8);
      acc += __shfl_down_sync(0xffffffffu, acc, 1, 8);
      if (j == 0){
        float v = b2s[o] + acc;
        h2_s[o] = v > 0.f ? v : expm1f(v);
      }
    }
    __syncthreads();

    // ---- Phase 4: 1x1 output conv (4 warps, one per out channel)
    if (tid < 128){
      int oc = tid >> 5, l = tid & 31;
      float partial = wos[oc*64 + l] * h2_s[l];
      partial = fmaf(wos[oc*64 + 32 + l], h2_s[32 + l], partial);
      partial += __shfl_down_sync(0xffffffffu, partial, 16, 32);
      partial += __shfl_down_sync(0xffffffffu, partial,  8, 32);
      partial += __shfl_down_sync(0xffffffffu, partial,  4, 32);
      partial += __shfl_down_sync(0xffffffffu, partial,  2, 32);
      partial += __shfl_down_sync(0xffffffffu, partial,  1, 32);
      if (l == 0){
        float v = bos[oc] + partial;
        if (rank) v *= 0.5f;          // logstd = made_output * 0.5
        myout[oc] = v;
      }
    }
    __syncthreads();

    // ---- Phase 5: exchange with partner CTA, then y[p] update
    const int par = p & 1;
    if (tid == 0){
      unsigned long long v0 = *(const unsigned long long*)&myout[0];
      unsigned long long v1 = *(const unsigned long long*)&myout[2];
      uint32_t peer = rank ^ 1u;
      uint32_t lbuf = smem_u32(&recvbuf[par][0]);
      uint32_t rbuf, rbar;
      asm volatile("mapa.shared::cluster.u32 %0, %1, %2;"
                   : "=r"(rbuf) : "r"(lbuf), "r"(peer));
      asm volatile("st.shared::cluster.b64 [%0], %1;"
                   :: "r"(rbuf), "l"(v0) : "memory");
      asm volatile("st.shared::cluster.b64 [%0], %1;"
                   :: "r"(rbuf + 8), "l"(v1) : "memory");
      uint32_t lbar = smem_u32(&mbar[par]);
      asm volatile("mapa.shared::cluster.u32 %0, %1, %2;"
                   : "=r"(rbar) : "r"(lbar), "r"(peer));
      asm volatile("mbarrier.arrive.release.cluster.shared::cluster.b64 _, [%0];"
                   :: "r"(rbar) : "memory");
      if (rank) lssum += myout[0] + myout[1] + myout[2] + myout[3];
    }
    if (tid < 4){
      uint32_t lbar = smem_u32(&mbar[par]);
      uint32_t phase = (uint32_t)((p >> 1) & 1);
      uint32_t done;
      do {
        asm volatile("{\n\t.reg .pred p;\n\t"
          "mbarrier.try_wait.parity.acquire.cluster.shared::cta.b64 p, [%1], %2, 0x989680;\n\t"
          "selp.b32 %0, 1, 0, p;\n\t}"
          : "=r"(done) : "r"(lbar), "r"(phase) : "memory");
      } while (!done);
      float other = recvbuf[par][tid];
      float mu_v = rank ? other      : myout[tid];
      float ls_v = rank ? myout[tid] : other;
      y_s[(p << 2) + tid] = (x_s[(p << 2) + tid] - mu_v) / (expf(ls_v) + ELU_EPS);
    }
    __syncthreads();
  }

  // ---- Outputs: y (rank 0) in NCHW, per-batch logstd sum (rank 1)
  if (rank == 0){
    for (int idx = tid; idx < 256; idx += 512){
      out[batch*256 + idx] = y_s[((idx & 63) << 2) + (idx >> 6)];
    }
  } else if (tid == 0 && out_n >= 8224){
    out[8192 + batch] = lssum;
  }

  asm volatile("barrier.cluster.arrive.aligned;" ::: "memory");
  asm volatile("barrier.cluster.wait.aligned;"   ::: "memory");
}

extern "C" void kernel_launch(void* const* d_in, const int* in_sizes, int n_in,
                              void* d_out, int out_size) {
  const float* p[17];
  for (int i = 0; i < 17 && i < n_in; i++) p[i] = (const float*)d_in[i];
  made_flow_kernel<<<64, 512>>>(
    p[0],
    p[1], p[2], p[3], p[4], p[5], p[6], p[7], p[8],
    p[9], p[10], p[11], p[12], p[13], p[14], p[15], p[16],
    (float*)d_out, out_size);
}

// round 3
// speedup vs baseline: 1.1102x; 1.1102x over previous
#include <cuda_runtime.h>
#include <cstdint>

// AF2dMADEBlock: exact sequential raster sweep (masks zero all future-pixel
// contributions, so the 64-step fixed-point scan == one raster pass).
// Cluster of 2 CTAs per batch (rank0 = mu net, rank1 = lv net), 512 thr/CTA.
// Per pixel: 3 phases / 3 barriers:
//   A: layer1 dot   B: layer2 dot
//   C: out-conv + per-warp DSMEM exchange + y update + h0[p+1] + gathers(p+1)
// Masked w1/w2 in registers (80 f32/thread). Fast-math exp/div.

#define EPS 1e-12f

__device__ __forceinline__ uint32_t smem_u32(const void* p){
  return (uint32_t)__cvta_generic_to_shared((void*)p);
}

__device__ __forceinline__ float elu_f(float x){
  return x > 0.f ? x : (__expf(x) - 1.f);
}

__global__ void __cluster_dims__(2,1,1) __launch_bounds__(512,1)
made_flow_kernel(const float* __restrict__ xg,
  const float* __restrict__ mw0, const float* __restrict__ mb0,
  const float* __restrict__ mw1, const float* __restrict__ mb1,
  const float* __restrict__ mw2, const float* __restrict__ mb2,
  const float* __restrict__ mwo, const float* __restrict__ mbo,
  const float* __restrict__ lw0, const float* __restrict__ lb0,
  const float* __restrict__ lw1, const float* __restrict__ lb1,
  const float* __restrict__ lw2, const float* __restrict__ lb2,
  const float* __restrict__ lwo, const float* __restrict__ lbo,
  float* __restrict__ out, int out_n)
{
  __shared__ __align__(16) float h0g[64*64];   // h0 over grid, [pix][ch]
  __shared__ __align__(16) float h1g[64*64];   // h1 over grid
  __shared__ __align__(16) float w0s[16*64];   // mask-A w0: [(tap*4+ic)][o]
  __shared__ __align__(16) float y_s[64*4];    // y, [pix][ch]
  __shared__ __align__(16) float x_s[64*4];    // x, [pix][ch]
  __shared__ __align__(16) float a1[320];      // layer1 window (5 taps x 64)
  __shared__ __align__(16) float a2[320];      // layer2 window
  __shared__ __align__(16) float h2s[64];
  __shared__ float b0s[64], b1s[64], b2s[64];
  __shared__ __align__(16) float wos[256];     // 1x1 out conv [oc][c]
  __shared__ float bos[4];
  __shared__ __align__(16) float ownout[2][4]; // own net outputs, dbl-buffered
  __shared__ __align__(16) float recv[2][4];   // peer net outputs
  __shared__ float ls4[4];
  __shared__ __align__(8) unsigned long long mbar[2];

  const int tid = threadIdx.x;
  uint32_t rank; asm("mov.u32 %0, %%cluster_ctarank;" : "=r"(rank));
  const int batch = blockIdx.x >> 1;

  const float* w0g = rank ? lw0 : mw0;
  const float* b0g = rank ? lb0 : mb0;
  const float* w1g = rank ? lw1 : mw1;
  const float* b1g = rank ? lb1 : mb1;
  const float* w2g = rank ? lw2 : mw2;
  const float* b2g = rank ? lb2 : mb2;
  const float* wog = rank ? lwo : mwo;
  const float* bog = rank ? lbo : mbo;

  if (tid == 0){
    // count = 8: 4 local release-arrives + 4 peer cluster release-arrives
    asm volatile("mbarrier.init.shared.b64 [%0], %1;"
                 :: "r"(smem_u32(&mbar[0])), "r"(8u) : "memory");
    asm volatile("mbarrier.init.shared.b64 [%0], %1;"
                 :: "r"(smem_u32(&mbar[1])), "r"(8u) : "memory");
  }

  // ---- Stage weights/biases/x into smem ----
  for (int idx = tid; idx < 1024; idx += 512){
    int r = idx >> 6, o = idx & 63;
    int t = r >> 2, ic = r & 3;
    int ky = (t == 3) ? 1 : 0;
    int kx = (t == 3) ? 0 : t;
    w0s[idx] = w0g[(o*4 + ic)*9 + ky*3 + kx];
  }
  if (tid < 64){
    float bv = b0g[tid];
    b0s[tid] = bv; b1s[tid] = b1g[tid]; b2s[tid] = b2g[tid];
    // prologue: h0[0] = ELU(b0) (no valid taps at pixel 0)
    float e = elu_f(bv);
    h0g[tid] = e;
    a1[256 + tid] = e;
  }
  if (tid < 256) wos[tid] = wog[tid];
  if (tid < 4)   bos[tid] = bog[tid];
  if (tid < 256){
    int pos = tid & 63, c = tid >> 6;
    x_s[pos*4 + c] = xg[batch*256 + tid];   // NCHW -> [pix][ch]
  }
  // zero a1/a2 tap regions (taps 0..3)
  if (tid < 128){
    float4 z = make_float4(0.f,0.f,0.f,0.f);
    if (tid < 64) *(float4*)&a1[tid << 2] = z;
    else          *(float4*)&a2[(tid - 64) << 2] = z;
  }

  // ---- Masked mask-B weights into registers ----
  // thread (o = tid>>3, j = tid&7) owns K-slice {4j+32i+m : i<10, m<4}
  const int o = tid >> 3;
  const int j = tid & 7;
  float4 w1r[10], w2r[10];
  #pragma unroll
  for (int i = 0; i < 10; i++){
    float t1[4], t2[4];
    #pragma unroll
    for (int m = 0; m < 4; m++){
      int k  = (j << 2) + (i << 5) + m;
      int t  = k >> 6, ic = k & 63;
      int ky = (t >= 3) ? 1 : 0;
      int kx = (t >= 3) ? (t - 3) : t;
      int gi = (o*64 + ic)*9 + ky*3 + kx;
      t1[m] = w1g[gi];
      t2[m] = w2g[gi];
    }
    w1r[i] = make_float4(t1[0], t1[1], t1[2], t1[3]);
    w2r[i] = make_float4(t2[0], t2[1], t2[2], t2[3]);
  }

  __syncthreads();
  asm volatile("barrier.cluster.arrive.aligned;" ::: "memory");
  asm volatile("barrier.cluster.wait.aligned;"   ::: "memory");

  float lsacc = 0.f;

  for (int p = 0; p < 64; p++){
    // ---- Phase A: h1[p] = ELU(W1 . a1 + b1) ----
    {
      float4 acc = make_float4(0.f,0.f,0.f,0.f);
      #pragma unroll
      for (int i = 0; i < 10; i++){
        float4 a = *(const float4*)&a1[(j << 2) + (i << 5)];
        acc.x = fmaf(w1r[i].x, a.x, acc.x);
        acc.y = fmaf(w1r[i].y, a.y, acc.y);
        acc.z = fmaf(w1r[i].z, a.z, acc.z);
        acc.w = fmaf(w1r[i].w, a.w, acc.w);
      }
      float s = (acc.x + acc.y) + (acc.z + acc.w);
      s += __shfl_down_sync(0xffffffffu, s, 4, 8);
      s += __shfl_down_sync(0xffffffffu, s, 2, 8);
      s += __shfl_down_sync(0xffffffffu, s, 1, 8);
      if (j == 0){
        float e = elu_f(b1s[o] + s);
        h1g[(p << 6) + o] = e;
        a2[256 + o] = e;
      }
    }
    __syncthreads();

    // ---- Phase B: h2[p] = ELU(W2 . a2 + b2) ----
    {
      float4 acc = make_float4(0.f,0.f,0.f,0.f);
      #pragma unroll
      for (int i = 0; i < 10; i++){
        float4 a = *(const float4*)&a2[(j << 2) + (i << 5)];
        acc.x = fmaf(w2r[i].x, a.x, acc.x);
        acc.y = fmaf(w2r[i].y, a.y, acc.y);
        acc.z = fmaf(w2r[i].z, a.z, acc.z);
        acc.w = fmaf(w2r[i].w, a.w, acc.w);
      }
      float s = (acc.x + acc.y) + (acc.z + acc.w);
      s += __shfl_down_sync(0xffffffffu, s, 4, 8);
      s += __shfl_down_sync(0xffffffffu, s, 2, 8);
      s += __shfl_down_sync(0xffffffffu, s, 1, 8);
      if (j == 0) h2s[o] = elu_f(b2s[o] + s);
    }
    __syncthreads();

    // ---- Phase C: out conv + exchange + y[p] + h0[p+1] + gathers(p+1) ----
    const int par = p & 1;
    const uint32_t parity = (uint32_t)((p >> 1) & 1);

    if (tid < 128){
      // out conv: warp oc in 0..3
      int oc = tid >> 5, l = tid & 31;
      float pr = fmaf(wos[oc*64 + 32 + l], h2s[32 + l], wos[oc*64 + l] * h2s[l]);
      pr += __shfl_down_sync(0xffffffffu, pr, 16, 32);
      pr += __shfl_down_sync(0xffffffffu, pr,  8, 32);
      pr += __shfl_down_sync(0xffffffffu, pr,  4, 32);
      pr += __shfl_down_sync(0xffffffffu, pr,  2, 32);
      pr += __shfl_down_sync(0xffffffffu, pr,  1, 32);
      if (l == 0){
        float v = bos[oc] + pr;
        if (rank){ v *= 0.5f; lsacc += v; }
        ownout[par][oc] = v;
        uint32_t peer = rank ^ 1u;
        uint32_t lrec = smem_u32(&recv[par][oc]);
        uint32_t rrec, rbar;
        asm volatile("mapa.shared::cluster.u32 %0, %1, %2;"
                     : "=r"(rrec) : "r"(lrec), "r"(peer));
        asm volatile("st.shared::cluster.f32 [%0], %1;"
                     :: "r"(rrec), "f"(v) : "memory");
        uint32_t lbar = smem_u32(&mbar[par]);
        asm volatile("mapa.shared::cluster.u32 %0, %1, %2;"
                     : "=r"(rbar) : "r"(lbar), "r"(peer));
        asm volatile("mbarrier.arrive.release.cluster.shared::cluster.b64 _, [%0];"
                     :: "r"(rbar) : "memory");
        asm volatile("mbarrier.arrive.release.cta.shared::cta.b64 _, [%0];"
                     :: "r"(lbar) : "memory");
      }
    } else if (tid < 256){
      // gathers for pixel p+1 (previous-row taps + (0,-1) tap from h0g/h1g)
      if (p < 63){
        int idx = tid - 128;
        int buf = idx >> 6;
        int v   = idx & 63;
        int t   = v >> 4, c4 = (v & 15) << 2;
        int pn = p + 1, pyn = pn >> 3, pxn = pn & 7;
        int qy = (t < 3) ? pyn - 1 : pyn;
        int qx = (t < 3) ? pxn - 1 + t : pxn - 1;
        float4 val = make_float4(0.f,0.f,0.f,0.f);
        const float* src = buf ? h1g : h0g;
        if ((unsigned)qy < 8u && (unsigned)qx < 8u)
          val = *(const float4*)&src[((qy*8 + qx) << 6) + c4];
        float* dst = buf ? a2 : a1;
        *(float4*)&dst[(t << 6) + c4] = val;
      }
    }

    if (tid < 64){
      // wait for peer (and local ordering) then compute y[p] in registers
      uint32_t lbar = smem_u32(&mbar[par]);
      uint32_t done;
      do {
        asm volatile("{\n\t.reg .pred p;\n\t"
          "mbarrier.try_wait.parity.acquire.cluster.shared::cta.b64 p, [%1], %2, 0x989680;\n\t"
          "selp.b32 %0, 1, 0, p;\n\t}"
          : "=r"(done) : "r"(lbar), "r"(parity) : "memory");
      } while (!done);

      float4 ov = *(const float4*)&ownout[par][0];
      float4 rv = *(const float4*)&recv[par][0];
      float4 xv = *(const float4*)&x_s[p << 2];
      float mu0 = rank ? rv.x : ov.x, ls0 = rank ? ov.x : rv.x;
      float mu1 = rank ? rv.y : ov.y, ls1 = rank ? ov.y : rv.y;
      float mu2 = rank ? rv.z : ov.z, ls2 = rank ? ov.z : rv.z;
      float mu3 = rank ? rv.w : ov.w, ls3 = rank ? ov.w : rv.w;
      float y0 = __fdividef(xv.x - mu0, __expf(ls0) + EPS);
      float y1 = __fdividef(xv.y - mu1, __expf(ls1) + EPS);
      float y2 = __fdividef(xv.z - mu2, __expf(ls2) + EPS);
      float y3 = __fdividef(xv.w - mu3, __expf(ls3) + EPS);
      if (tid < 4){
        float w = (tid == 0) ? y0 : (tid == 1) ? y1 : (tid == 2) ? y2 : y3;
        y_s[(p << 2) + tid] = w;
      }
      if (p < 63){
        // h0[p+1]: 3 previous-row taps from y_s + fresh (0,-1) tap from regs
        int pn = p + 1, pyn = pn >> 3, pxn = pn & 7;
        float acc = b0s[tid];
        #pragma unroll
        for (int t = 0; t < 3; t++){
          int qy = pyn - 1, qx = pxn - 1 + t;
          if ((unsigned)qy < 8u && (unsigned)qx < 8u){
            float4 yq = *(const float4*)&y_s[(qy*8 + qx) << 2];
            acc = fmaf(w0s[(t*4 + 0)*64 + tid], yq.x, acc);
            acc = fmaf(w0s[(t*4 + 1)*64 + tid], yq.y, acc);
            acc = fmaf(w0s[(t*4 + 2)*64 + tid], yq.z, acc);
            acc = fmaf(w0s[(t*4 + 3)*64 + tid], yq.w, acc);
          }
        }
        if (pxn != 0){
          acc = fmaf(w0s[12*64 + tid], y0, acc);
          acc = fmaf(w0s[13*64 + tid], y1, acc);
          acc = fmaf(w0s[14*64 + tid], y2, acc);
          acc = fmaf(w0s[15*64 + tid], y3, acc);
        }
        float e = elu_f(acc);
        h0g[(pn << 6) + tid] = e;
        a1[256 + tid] = e;
      }
    }
    __syncthreads();
  }

  // ---- Outputs ----
  if (rank == 0){
    for (int idx = tid; idx < 256; idx += 512)
      out[batch*256 + idx] = y_s[((idx & 63) << 2) + (idx >> 6)];
  } else {
    if (tid < 128 && (tid & 31) == 0) ls4[tid >> 5] = lsacc;
    __syncthreads();
    if (tid == 0 && out_n >= 8224)
      out[8192 + batch] = (ls4[0] + ls4[1]) + (ls4[2] + ls4[3]);
  }

  asm volatile("barrier.cluster.arrive.aligned;" ::: "memory");
  asm volatile("barrier.cluster.wait.aligned;"   ::: "memory");
}

extern "C" void kernel_launch(void* const* d_in, const int* in_sizes, int n_in,
                              void* d_out, int out_size) {
  const float* p[17];
  for (int i = 0; i < 17 && i < n_in; i++) p[i] = (const float*)d_in[i];
  made_flow_kernel<<<64, 512>>>(
    p[0],
    p[1], p[2], p[3], p[4], p[5], p[6], p[7], p[8],
    p[9], p[10], p[11], p[12], p[13], p[14], p[15], p[16],
    (float*)d_out, out_size);
}

// round 4
// speedup vs baseline: 1.1316x; 1.0193x over previous
#include <cuda_runtime.h>
#include <cstdint>

// AF2dMADEBlock: exact sequential raster sweep.
// Cluster of 2 CTAs per batch (rank0 = mu, rank1 = lv), 512 thr/CTA.
// Pipelined tap-split: past-tap partial dots (taps 0-3, 256/320 of the work)
// for pixel p+1 are computed during phase C of pixel p, overlapping the DSMEM
// exchange wait. Phases A/B only do the center-tap (64/320) + reduction.
// All dot FMAs are packed f32x2 (FFMA2) to halve issue cost.

#define EPS 1e-12f
typedef unsigned long long ull;

__device__ __forceinline__ uint32_t smem_u32(const void* p){
  return (uint32_t)__cvta_generic_to_shared((void*)p);
}
__device__ __forceinline__ float elu_f(float x){
  return x > 0.f ? x : (__expf(x) - 1.f);
}
__device__ __forceinline__ void fma2(ull& acc, ull a, ull b){
  asm("fma.rn.f32x2 %0, %1, %2, %0;" : "+l"(acc) : "l"(a), "l"(b));
}
__device__ __forceinline__ ull pack2(float lo, float hi){
  ull r; asm("mov.b64 %0, {%1, %2};" : "=l"(r) : "f"(lo), "f"(hi)); return r;
}
__device__ __forceinline__ float hsum2x2(ull a, ull b){
  float ax, ay, bx, by;
  asm("mov.b64 {%0, %1}, %2;" : "=f"(ax), "=f"(ay) : "l"(a));
  asm("mov.b64 {%0, %1}, %2;" : "=f"(bx), "=f"(by) : "l"(b));
  return (ax + ay) + (bx + by);
}

__global__ void __cluster_dims__(2,1,1) __launch_bounds__(512,1)
made_flow_kernel(const float* __restrict__ xg,
  const float* __restrict__ mw0, const float* __restrict__ mb0,
  const float* __restrict__ mw1, const float* __restrict__ mb1,
  const float* __restrict__ mw2, const float* __restrict__ mb2,
  const float* __restrict__ mwo, const float* __restrict__ mbo,
  const float* __restrict__ lw0, const float* __restrict__ lb0,
  const float* __restrict__ lw1, const float* __restrict__ lb1,
  const float* __restrict__ lw2, const float* __restrict__ lb2,
  const float* __restrict__ lwo, const float* __restrict__ lbo,
  float* __restrict__ out, int out_n)
{
  // rows 0..63 = pixels, row 64 = zero dummy (OOB taps)
  __shared__ __align__(16) float h0g[65*64];
  __shared__ __align__(16) float h1g[65*64];
  __shared__ __align__(16) float w0s[16*64];   // mask-A w0: [(tap*4+ic)][o]
  __shared__ __align__(16) float y_s[64*4];
  __shared__ __align__(16) float x_s[64*4];
  __shared__ __align__(16) float h2s[64];
  __shared__ float b0s[64], b1s[64], b2s[64];
  __shared__ __align__(16) float wos[256];
  __shared__ float bos[4];
  __shared__ __align__(16) float ownout[2][4];
  __shared__ __align__(16) float recv[2][4];
  __shared__ float ls4[4];
  __shared__ __align__(8) unsigned long long mbar[2];

  const int tid = threadIdx.x;
  uint32_t rank; asm("mov.u32 %0, %%cluster_ctarank;" : "=r"(rank));
  const int batch = blockIdx.x >> 1;

  const float* w0g = rank ? lw0 : mw0;
  const float* b0g = rank ? lb0 : mb0;
  const float* w1g = rank ? lw1 : mw1;
  const float* b1g = rank ? lb1 : mb1;
  const float* w2g = rank ? lw2 : mw2;
  const float* b2g = rank ? lb2 : mb2;
  const float* wog = rank ? lwo : mwo;
  const float* bog = rank ? lbo : mbo;

  if (tid == 0){
    asm volatile("mbarrier.init.shared.b64 [%0], %1;"
                 :: "r"(smem_u32(&mbar[0])), "r"(8u) : "memory");
    asm volatile("mbarrier.init.shared.b64 [%0], %1;"
                 :: "r"(smem_u32(&mbar[1])), "r"(8u) : "memory");
  }

  // ---- Stage small weights/biases/x; zero dummy rows ----
  for (int idx = tid; idx < 1024; idx += 512){
    int r = idx >> 6, oo = idx & 63;
    int t = r >> 2, ic = r & 3;
    int ky = (t == 3) ? 1 : 0;
    int kx = (t == 3) ? 0 : t;
    w0s[idx] = w0g[(oo*4 + ic)*9 + ky*3 + kx];
  }
  if (tid < 64){
    float bv = b0g[tid];
    b0s[tid] = bv; b1s[tid] = b1g[tid]; b2s[tid] = b2g[tid];
    float e = elu_f(bv);          // h0[0]: no valid taps at pixel 0
    h0g[tid] = e;
    h0g[64*64 + tid] = 0.f;       // dummy rows
    h1g[64*64 + tid] = 0.f;
  }
  if (tid < 256) wos[tid] = wog[tid];
  if (tid < 4)   bos[tid] = bog[tid];
  if (tid < 256){
    int pos = tid & 63, c = tid >> 6;
    x_s[pos*4 + c] = xg[batch*256 + tid];
  }

  // ---- Masked mask-B weights, packed f32x2, into registers ----
  // thread (o = tid>>3, j = tid&7): i-th chunk covers k = 4j + 32i + {0..3};
  // i in 0..7 -> taps 0..3 (tap = i>>1, ofs = 4j + (i&1)*32), i in 8..9 -> center.
  const int o = tid >> 3;
  const int j = tid & 7;
  ull w1p[20], w2p[20];
  #pragma unroll
  for (int i = 0; i < 10; i++){
    float t1[4], t2[4];
    #pragma unroll
    for (int m = 0; m < 4; m++){
      int k  = (j << 2) + (i << 5) + m;
      int t  = k >> 6, ic = k & 63;
      int ky = (t >= 3) ? 1 : 0;
      int kx = (t >= 3) ? (t - 3) : t;
      int gi = (o*64 + ic)*9 + ky*3 + kx;
      t1[m] = w1g[gi];
      t2[m] = w2g[gi];
    }
    w1p[2*i]   = pack2(t1[0], t1[1]);
    w1p[2*i+1] = pack2(t1[2], t1[3]);
    w2p[2*i]   = pack2(t2[0], t2[1]);
    w2p[2*i+1] = pack2(t2[2], t2[3]);
  }

  __syncthreads();
  asm volatile("barrier.cluster.arrive.aligned;" ::: "memory");
  asm volatile("barrier.cluster.wait.aligned;"   ::: "memory");

  float lsacc = 0.f;
  // past-tap partials for pixel 0: all taps OOB -> zero
  ull pA0 = 0ull, pA1 = 0ull, pB0 = 0ull, pB1 = 0ull;
  const int joff = j << 2;

  for (int p = 0; p < 64; p++){
    // ---- Phase A: h1[p] = ELU(partial + center-dot + b1) ----
    {
      ull a01 = pA0, a23 = pA1;
      const ull* c0 = (const ull*)&h0g[(p << 6) + joff];
      const ull* c1 = (const ull*)&h0g[(p << 6) + joff + 32];
      ull x0 = c0[0], x1 = c0[1], x2 = c1[0], x3 = c1[1];
      fma2(a01, w1p[16], x0); fma2(a23, w1p[17], x1);
      fma2(a01, w1p[18], x2); fma2(a23, w1p[19], x3);
      float s = hsum2x2(a01, a23);
      s += __shfl_xor_sync(0xffffffffu, s, 4, 8);
      s += __shfl_xor_sync(0xffffffffu, s, 2, 8);
      s += __shfl_xor_sync(0xffffffffu, s, 1, 8);
      if (j == 0) h1g[(p << 6) + o] = elu_f(b1s[o] + s);
    }
    __syncthreads();

    // ---- Phase B: h2[p] = ELU(partial + center-dot + b2) ----
    {
      ull a01 = pB0, a23 = pB1;
      const ull* c0 = (const ull*)&h1g[(p << 6) + joff];
      const ull* c1 = (const ull*)&h1g[(p << 6) + joff + 32];
      ull x0 = c0[0], x1 = c0[1], x2 = c1[0], x3 = c1[1];
      fma2(a01, w2p[16], x0); fma2(a23, w2p[17], x1);
      fma2(a01, w2p[18], x2); fma2(a23, w2p[19], x3);
      float s = hsum2x2(a01, a23);
      s += __shfl_xor_sync(0xffffffffu, s, 4, 8);
      s += __shfl_xor_sync(0xffffffffu, s, 2, 8);
      s += __shfl_xor_sync(0xffffffffu, s, 1, 8);
      if (j == 0) h2s[o] = elu_f(b2s[o] + s);
    }
    __syncthreads();

    // ---- Phase C: out conv + exchange (overlapped with p+1 partials) ----
    const int par = p & 1;
    const uint32_t parity = (uint32_t)((p >> 1) & 1);

    if (tid < 128){
      int oc = tid >> 5, l = tid & 31;
      float pr = fmaf(wos[oc*64 + 32 + l], h2s[32 + l], wos[oc*64 + l] * h2s[l]);
      pr += __shfl_down_sync(0xffffffffu, pr, 16, 32);
      pr += __shfl_down_sync(0xffffffffu, pr,  8, 32);
      pr += __shfl_down_sync(0xffffffffu, pr,  4, 32);
      pr += __shfl_down_sync(0xffffffffu, pr,  2, 32);
      pr += __shfl_down_sync(0xffffffffu, pr,  1, 32);
      if (l == 0){
        float v = bos[oc] + pr;
        if (rank){ v *= 0.5f; lsacc += v; }
        ownout[par][oc] = v;
        uint32_t peer = rank ^ 1u;
        uint32_t lrec = smem_u32(&recv[par][oc]);
        uint32_t rrec, rbar;
        asm volatile("mapa.shared::cluster.u32 %0, %1, %2;"
                     : "=r"(rrec) : "r"(lrec), "r"(peer));
        asm volatile("st.shared::cluster.f32 [%0], %1;"
                     :: "r"(rrec), "f"(v) : "memory");
        uint32_t lbar = smem_u32(&mbar[par]);
        asm volatile("mapa.shared::cluster.u32 %0, %1, %2;"
                     : "=r"(rbar) : "r"(lbar), "r"(peer));
        asm volatile("mbarrier.arrive.release.cluster.shared::cluster.b64 _, [%0];"
                     :: "r"(rbar) : "memory");
        asm volatile("mbarrier.arrive.release.cta.shared::cta.b64 _, [%0];"
                     :: "r"(lbar) : "memory");
      }
    }

    // past-tap partial dots for pixel p+1 (layers 1 and 2), hides exchange wait
    if (p < 63){
      const int pn = p + 1, pyn = pn >> 3, pxn = pn & 7;
      int q[4];
      #pragma unroll
      for (int t = 0; t < 3; t++){
        int qy = pyn - 1, qx = pxn - 1 + t;
        q[t] = ((unsigned)qy < 8u && (unsigned)qx < 8u) ? (qy*8 + qx) : 64;
      }
      q[3] = (pxn != 0) ? (pn - 1) : 64;
      ull A0 = 0ull, A1 = 0ull, B0 = 0ull, B1 = 0ull;
      #pragma unroll
      for (int i = 0; i < 8; i++){
        int ofs = (q[i >> 1] << 6) + joff + ((i & 1) << 5);
        const ull* s0 = (const ull*)&h0g[ofs];
        const ull* s1 = (const ull*)&h1g[ofs];
        ull a0 = s0[0], a1v = s0[1];
        ull b0 = s1[0], b1v = s1[1];
        fma2(A0, w1p[2*i], a0); fma2(A1, w1p[2*i+1], a1v);
        fma2(B0, w2p[2*i], b0); fma2(B1, w2p[2*i+1], b1v);
      }
      pA0 = A0; pA1 = A1; pB0 = B0; pB1 = B1;
    }

    if (tid < 64){
      uint32_t lbar = smem_u32(&mbar[par]);
      uint32_t done;
      do {
        asm volatile("{\n\t.reg .pred p;\n\t"
          "mbarrier.try_wait.parity.acquire.cluster.shared::cta.b64 p, [%1], %2, 0x989680;\n\t"
          "selp.b32 %0, 1, 0, p;\n\t}"
          : "=r"(done) : "r"(lbar), "r"(parity) : "memory");
      } while (!done);

      float4 ov = *(const float4*)&ownout[par][0];
      float4 rv = *(const float4*)&recv[par][0];
      float4 xv = *(const float4*)&x_s[p << 2];
      float mu0 = rank ? rv.x : ov.x, ls0 = rank ? ov.x : rv.x;
      float mu1 = rank ? rv.y : ov.y, ls1 = rank ? ov.y : rv.y;
      float mu2 = rank ? rv.z : ov.z, ls2 = rank ? ov.z : rv.z;
      float mu3 = rank ? rv.w : ov.w, ls3 = rank ? ov.w : rv.w;
      float y0 = __fdividef(xv.x - mu0, __expf(ls0) + EPS);
      float y1 = __fdividef(xv.y - mu1, __expf(ls1) + EPS);
      float y2 = __fdividef(xv.z - mu2, __expf(ls2) + EPS);
      float y3 = __fdividef(xv.w - mu3, __expf(ls3) + EPS);
      if (tid < 4){
        float w = (tid == 0) ? y0 : (tid == 1) ? y1 : (tid == 2) ? y2 : y3;
        y_s[(p << 2) + tid] = w;
      }
      if (p < 63){
        int pn = p + 1, pyn = pn >> 3, pxn = pn & 7;
        float acc = b0s[tid];
        #pragma unroll
        for (int t = 0; t < 3; t++){
          int qy = pyn - 1, qx = pxn - 1 + t;
          if ((unsigned)qy < 8u && (unsigned)qx < 8u){
            float4 yq = *(const float4*)&y_s[(qy*8 + qx) << 2];
            acc = fmaf(w0s[(t*4 + 0)*64 + tid], yq.x, acc);
            acc = fmaf(w0s[(t*4 + 1)*64 + tid], yq.y, acc);
            acc = fmaf(w0s[(t*4 + 2)*64 + tid], yq.z, acc);
            acc = fmaf(w0s[(t*4 + 3)*64 + tid], yq.w, acc);
          }
        }
        if (pxn != 0){
          acc = fmaf(w0s[12*64 + tid], y0, acc);
          acc = fmaf(w0s[13*64 + tid], y1, acc);
          acc = fmaf(w0s[14*64 + tid], y2, acc);
          acc = fmaf(w0s[15*64 + tid], y3, acc);
        }
        h0g[(pn << 6) + tid] = elu_f(acc);
      }
    }
    __syncthreads();
  }

  // ---- Outputs ----
  if (rank == 0){
    for (int idx = tid; idx < 256; idx += 512)
      out[batch*256 + idx] = y_s[((idx & 63) << 2) + (idx >> 6)];
  } else {
    if (tid < 128 && (tid & 31) == 0) ls4[tid >> 5] = lsacc;
    __syncthreads();
    if (tid == 0 && out_n >= 8224)
      out[8192 + batch] = (ls4[0] + ls4[1]) + (ls4[2] + ls4[3]);
  }

  asm volatile("barrier.cluster.arrive.aligned;" ::: "memory");
  asm volatile("barrier.cluster.wait.aligned;"   ::: "memory");
}

extern "C" void kernel_launch(void* const* d_in, const int* in_sizes, int n_in,
                              void* d_out, int out_size) {
  const float* p[17];
  for (int i = 0; i < 17 && i < n_in; i++) p[i] = (const float*)d_in[i];
  made_flow_kernel<<<64, 512>>>(
    p[0],
    p[1], p[2], p[3], p[4], p[5], p[6], p[7], p[8],
    p[9], p[10], p[11], p[12], p[13], p[14], p[15], p[16],
    (float*)d_out, out_size);
}